// round 1
// baseline (speedup 1.0000x reference)
#include <cuda_runtime.h>
#include <cstdint>

#define BM      128       // rows per tile
#define KDIM    64
#define NDIM    128
#define XPAD    68        // padded x row stride (floats) — breaks 32-bank aliasing
#define THREADS 256
#define MAXGRID 296       // 2 persistent CTAs per SM x 148 SMs

// smem layout (floats):
// [0, 8192)            : Bfrag — 8 ksteps * 16 ntiles * 32 lanes * float2 (tf32 bits)
// [8192, 8320)         : bias (128)
// [8320, 8320+2*128*68): x double buffer
#define SMEM_FLOATS (8192 + 128 + 2 * BM * XPAD)
#define SMEM_BYTES  (SMEM_FLOATS * 4)

__device__ __forceinline__ uint32_t f2tf32(float f) {
    uint32_t r;
    asm("cvt.rna.tf32.f32 %0, %1;" : "=r"(r) : "f"(f));
    return r;
}

__device__ __forceinline__ void issue_tile(const float* __restrict__ x,
                                           float* xsbuf, long tile_row,
                                           long M, int tid) {
    #pragma unroll
    for (int j = 0; j < 8; ++j) {
        int idx = tid + j * THREADS;       // 0..2047
        int row = idx >> 4;                // 0..127
        int c4  = idx & 15;                // 0..15 (float4 column)
        long grow = tile_row + row;
        bool valid = (grow < M);
        const float* src = x + (valid ? grow : 0) * KDIM + c4 * 4;
        uint32_t dst = (uint32_t)__cvta_generic_to_shared(xsbuf + row * XPAD + c4 * 4);
        int sz = valid ? 16 : 0;           // zfill rows past M
        asm volatile("cp.async.cg.shared.global [%0], [%1], 16, %2;\n"
                     :: "r"(dst), "l"(src), "r"(sz));
    }
}

extern __shared__ float smem[];

__global__ void __launch_bounds__(THREADS, 2)
dense_ragged_kernel(const float* __restrict__ x,
                    const float* __restrict__ W,
                    const float* __restrict__ bias,
                    float* __restrict__ out,
                    long M, int ntiles)
{
    float2* Bfrag = (float2*)smem;          // 4096 float2
    float*  bsm   = smem + 8192;            // 128
    float*  xs    = smem + 8192 + 128;      // 2 * BM * XPAD

    const int tid  = threadIdx.x;
    const int lane = tid & 31;
    const int wid  = tid >> 5;
    const int warp_m = wid & 3;             // 4 row bands of 32
    const int warp_n = wid >> 2;            // 2 col bands of 64
    const int qrow = lane >> 2;             // 0..7
    const int qk   = lane & 3;              // 0..3

    // ---- one-time per CTA: bias + W fragment precompute (tf32, lane layout) ----
    if (tid < 128) bsm[tid] = bias[tid];
    #pragma unroll
    for (int j = 0; j < 16; ++j) {
        int idx = tid + j * THREADS;        // 0..4095
        int li  = idx & 31;
        int nt  = (idx >> 5) & 15;
        int ks  = idx >> 9;
        // k-permutation sigma: phys col c<4 -> logical 2c ; c>=4 -> logical 2(c-4)+1
        int k0 = ks * 8 + 2 * (li & 3);
        int n  = nt * 8 + (li >> 2);
        uint32_t t0 = f2tf32(W[k0 * NDIM + n]);
        uint32_t t1 = f2tf32(W[(k0 + 1) * NDIM + n]);
        Bfrag[idx] = make_float2(__uint_as_float(t0), __uint_as_float(t1));
    }
    __syncthreads();

    // ---- persistent loop over row tiles ----
    int it  = blockIdx.x;
    int buf = 0;
    if (it < ntiles) {
        issue_tile(x, xs, (long)it * BM, M, tid);
        asm volatile("cp.async.commit_group;\n");
    }

    while (it < ntiles) {
        int next = it + gridDim.x;
        if (next < ntiles) {
            issue_tile(x, xs + (buf ^ 1) * (BM * XPAD), (long)next * BM, M, tid);
            asm volatile("cp.async.commit_group;\n");
            asm volatile("cp.async.wait_group 1;\n");
        } else {
            asm volatile("cp.async.wait_group 0;\n");
        }
        __syncthreads();

        const float* xb = xs + buf * (BM * XPAD);
        float acc[2][8][4];
        #pragma unroll
        for (int mt = 0; mt < 2; ++mt)
            #pragma unroll
            for (int nt = 0; nt < 8; ++nt)
                #pragma unroll
                for (int e = 0; e < 4; ++e) acc[mt][nt][e] = 0.f;

        #pragma unroll
        for (int ks = 0; ks < 8; ++ks) {
            uint32_t a[2][4];
            #pragma unroll
            for (int mt = 0; mt < 2; ++mt) {
                int r = warp_m * 32 + mt * 16 + qrow;
                float2 v0 = *(const float2*)(xb + r * XPAD + ks * 8 + 2 * qk);
                float2 v1 = *(const float2*)(xb + (r + 8) * XPAD + ks * 8 + 2 * qk);
                a[mt][0] = f2tf32(v0.x);
                a[mt][2] = f2tf32(v0.y);
                a[mt][1] = f2tf32(v1.x);
                a[mt][3] = f2tf32(v1.y);
            }
            #pragma unroll
            for (int nt = 0; nt < 8; ++nt) {
                float2 w = Bfrag[(ks * 16 + warp_n * 8 + nt) * 32 + lane];
                uint32_t b0 = __float_as_uint(w.x);
                uint32_t b1 = __float_as_uint(w.y);
                #pragma unroll
                for (int mt = 0; mt < 2; ++mt) {
                    asm volatile(
                        "mma.sync.aligned.m16n8k8.row.col.f32.tf32.tf32.f32 "
                        "{%0,%1,%2,%3}, {%4,%5,%6,%7}, {%8,%9}, {%0,%1,%2,%3};\n"
                        : "+f"(acc[mt][nt][0]), "+f"(acc[mt][nt][1]),
                          "+f"(acc[mt][nt][2]), "+f"(acc[mt][nt][3])
                        : "r"(a[mt][0]), "r"(a[mt][1]), "r"(a[mt][2]), "r"(a[mt][3]),
                          "r"(b0), "r"(b1));
                }
            }
        }
        __syncthreads();   // all lanes done reading xb before next iter overwrites it

        // ---- epilogue: bias + relu + store ----
        long baser = (long)it * BM + warp_m * 32;
        #pragma unroll
        for (int mt = 0; mt < 2; ++mt) {
            long r0 = baser + mt * 16 + qrow;
            long r1 = r0 + 8;
            #pragma unroll
            for (int nt = 0; nt < 8; ++nt) {
                int c = warp_n * 64 + nt * 8 + qk * 2;
                float b0v = bsm[c], b1v = bsm[c + 1];
                if (r0 < M) {
                    float2 o;
                    o.x = fmaxf(acc[mt][nt][0] + b0v, 0.f);
                    o.y = fmaxf(acc[mt][nt][1] + b1v, 0.f);
                    *(float2*)(out + r0 * NDIM + c) = o;
                }
                if (r1 < M) {
                    float2 o;
                    o.x = fmaxf(acc[mt][nt][2] + b0v, 0.f);
                    o.y = fmaxf(acc[mt][nt][3] + b1v, 0.f);
                    *(float2*)(out + r1 * NDIM + c) = o;
                }
            }
        }

        it = next;
        buf ^= 1;
    }
}

extern "C" void kernel_launch(void* const* d_in, const int* in_sizes, int n_in,
                              void* d_out, int out_size) {
    const float* x = (const float*)d_in[0];
    const float* W = (const float*)d_in[1];
    const float* b = (const float*)d_in[2];
    float* out = (float*)d_out;

    long M = (long)in_sizes[0] / KDIM;
    int ntiles = (int)((M + BM - 1) / BM);
    int grid = ntiles < MAXGRID ? ntiles : MAXGRID;

    cudaFuncSetAttribute(dense_ragged_kernel,
                         cudaFuncAttributeMaxDynamicSharedMemorySize, SMEM_BYTES);
    dense_ragged_kernel<<<grid, THREADS, SMEM_BYTES>>>(x, W, b, out, M, ntiles);
}

// round 2
// speedup vs baseline: 1.0002x; 1.0002x over previous
#include <cuda_runtime.h>
#include <cstdint>

#define BM      128       // rows per tile
#define KDIM    64
#define NDIM    128
#define XPAD    68        // padded x row stride (floats) — breaks 32-bank aliasing
#define THREADS 256
#define MAXGRID 296       // 2 persistent CTAs per SM x 148 SMs

// smem layout (floats):
// [0, 8192)            : Bfrag — 8 ksteps * 16 ntiles * 32 lanes * float2 (tf32 bits)
// [8192, 8320)         : bias (128)
// [8320, 8320+2*128*68): x double buffer
#define SMEM_FLOATS (8192 + 128 + 2 * BM * XPAD)
#define SMEM_BYTES  (SMEM_FLOATS * 4)

__device__ __forceinline__ uint32_t f2tf32(float f) {
    uint32_t r;
    asm("cvt.rna.tf32.f32 %0, %1;" : "=r"(r) : "f"(f));
    return r;
}

__device__ __forceinline__ void issue_tile(const float* __restrict__ x,
                                           float* xsbuf, long tile_row,
                                           long M, int tid) {
    #pragma unroll
    for (int j = 0; j < 8; ++j) {
        int idx = tid + j * THREADS;       // 0..2047
        int row = idx >> 4;                // 0..127
        int c4  = idx & 15;                // 0..15 (float4 column)
        long grow = tile_row + row;
        bool valid = (grow < M);
        const float* src = x + (valid ? grow : 0) * KDIM + c4 * 4;
        uint32_t dst = (uint32_t)__cvta_generic_to_shared(xsbuf + row * XPAD + c4 * 4);
        int sz = valid ? 16 : 0;           // zfill rows past M
        asm volatile("cp.async.cg.shared.global [%0], [%1], 16, %2;\n"
                     :: "r"(dst), "l"(src), "r"(sz));
    }
}

extern __shared__ float smem[];

__global__ void __launch_bounds__(THREADS, 2)
dense_ragged_kernel(const float* __restrict__ x,
                    const float* __restrict__ W,
                    const float* __restrict__ bias,
                    float* __restrict__ out,
                    long M, int ntiles)
{
    float2* Bfrag = (float2*)smem;          // 4096 float2
    float*  bsm   = smem + 8192;            // 128
    float*  xs    = smem + 8192 + 128;      // 2 * BM * XPAD

    const int tid  = threadIdx.x;
    const int lane = tid & 31;
    const int wid  = tid >> 5;
    const int warp_m = wid & 3;             // 4 row bands of 32
    const int warp_n = wid >> 2;            // 2 col bands of 64
    const int qrow = lane >> 2;             // 0..7
    const int qk   = lane & 3;              // 0..3

    // ---- one-time per CTA: bias + W fragment precompute (tf32, lane layout) ----
    if (tid < 128) bsm[tid] = bias[tid];
    #pragma unroll
    for (int j = 0; j < 16; ++j) {
        int idx = tid + j * THREADS;        // 0..4095
        int li  = idx & 31;
        int nt  = (idx >> 5) & 15;
        int ks  = idx >> 9;
        // k-permutation sigma: phys col c<4 -> logical 2c ; c>=4 -> logical 2(c-4)+1
        int k0 = ks * 8 + 2 * (li & 3);
        int n  = nt * 8 + (li >> 2);
        uint32_t t0 = f2tf32(W[k0 * NDIM + n]);
        uint32_t t1 = f2tf32(W[(k0 + 1) * NDIM + n]);
        Bfrag[idx] = make_float2(__uint_as_float(t0), __uint_as_float(t1));
    }
    __syncthreads();

    // ---- persistent loop over row tiles ----
    int it  = blockIdx.x;
    int buf = 0;
    if (it < ntiles) {
        issue_tile(x, xs, (long)it * BM, M, tid);
        asm volatile("cp.async.commit_group;\n");
    }

    while (it < ntiles) {
        int next = it + gridDim.x;
        if (next < ntiles) {
            issue_tile(x, xs + (buf ^ 1) * (BM * XPAD), (long)next * BM, M, tid);
            asm volatile("cp.async.commit_group;\n");
            asm volatile("cp.async.wait_group 1;\n");
        } else {
            asm volatile("cp.async.wait_group 0;\n");
        }
        __syncthreads();

        const float* xb = xs + buf * (BM * XPAD);
        float acc[2][8][4];
        #pragma unroll
        for (int mt = 0; mt < 2; ++mt)
            #pragma unroll
            for (int nt = 0; nt < 8; ++nt)
                #pragma unroll
                for (int e = 0; e < 4; ++e) acc[mt][nt][e] = 0.f;

        #pragma unroll
        for (int ks = 0; ks < 8; ++ks) {
            uint32_t a[2][4];
            #pragma unroll
            for (int mt = 0; mt < 2; ++mt) {
                int r = warp_m * 32 + mt * 16 + qrow;
                float2 v0 = *(const float2*)(xb + r * XPAD + ks * 8 + 2 * qk);
                float2 v1 = *(const float2*)(xb + (r + 8) * XPAD + ks * 8 + 2 * qk);
                a[mt][0] = f2tf32(v0.x);
                a[mt][2] = f2tf32(v0.y);
                a[mt][1] = f2tf32(v1.x);
                a[mt][3] = f2tf32(v1.y);
            }
            #pragma unroll
            for (int nt = 0; nt < 8; ++nt) {
                float2 w = Bfrag[(ks * 16 + warp_n * 8 + nt) * 32 + lane];
                uint32_t b0 = __float_as_uint(w.x);
                uint32_t b1 = __float_as_uint(w.y);
                #pragma unroll
                for (int mt = 0; mt < 2; ++mt) {
                    asm volatile(
                        "mma.sync.aligned.m16n8k8.row.col.f32.tf32.tf32.f32 "
                        "{%0,%1,%2,%3}, {%4,%5,%6,%7}, {%8,%9}, {%0,%1,%2,%3};\n"
                        : "+f"(acc[mt][nt][0]), "+f"(acc[mt][nt][1]),
                          "+f"(acc[mt][nt][2]), "+f"(acc[mt][nt][3])
                        : "r"(a[mt][0]), "r"(a[mt][1]), "r"(a[mt][2]), "r"(a[mt][3]),
                          "r"(b0), "r"(b1));
                }
            }
        }
        __syncthreads();   // all lanes done reading xb before next iter overwrites it

        // ---- epilogue: bias + relu + store ----
        long baser = (long)it * BM + warp_m * 32;
        #pragma unroll
        for (int mt = 0; mt < 2; ++mt) {
            long r0 = baser + mt * 16 + qrow;
            long r1 = r0 + 8;
            #pragma unroll
            for (int nt = 0; nt < 8; ++nt) {
                int c = warp_n * 64 + nt * 8 + qk * 2;
                float b0v = bsm[c], b1v = bsm[c + 1];
                if (r0 < M) {
                    float2 o;
                    o.x = fmaxf(acc[mt][nt][0] + b0v, 0.f);
                    o.y = fmaxf(acc[mt][nt][1] + b1v, 0.f);
                    *(float2*)(out + r0 * NDIM + c) = o;
                }
                if (r1 < M) {
                    float2 o;
                    o.x = fmaxf(acc[mt][nt][2] + b0v, 0.f);
                    o.y = fmaxf(acc[mt][nt][3] + b1v, 0.f);
                    *(float2*)(out + r1 * NDIM + c) = o;
                }
            }
        }

        it = next;
        buf ^= 1;
    }
}

extern "C" void kernel_launch(void* const* d_in, const int* in_sizes, int n_in,
                              void* d_out, int out_size) {
    const float* x = (const float*)d_in[0];
    const float* W = (const float*)d_in[1];
    const float* b = (const float*)d_in[2];
    float* out = (float*)d_out;

    long M = (long)in_sizes[0] / KDIM;
    int ntiles = (int)((M + BM - 1) / BM);
    int grid = ntiles < MAXGRID ? ntiles : MAXGRID;

    cudaFuncSetAttribute(dense_ragged_kernel,
                         cudaFuncAttributeMaxDynamicSharedMemorySize, SMEM_BYTES);
    dense_ragged_kernel<<<grid, THREADS, SMEM_BYTES>>>(x, W, b, out, M, ntiles);
}